// round 13
// baseline (speedup 1.0000x reference)
#include <cuda_runtime.h>
#include <cuda_bf16.h>
#include <cstdint>

// ---------------------------------------------------------------------------
// SpatialGraphConv (R10 structure + float2 x-staging with skewed layout):
//   k_z1/k_z2: zero colsum / Gs (also shift ncu capture slot onto k_pass1)
//   k_prep : zero G copies
//   k_pass1: x tile (float2 loads, skewed smem) -> xg = x@adj (8c x 5w reg
//            tiles) -> split bf16 -> packed uint4 SW128 stores; fused exact
//            colsum; spill tiles to scratch; Gram via HMMA (G1 triangle only)
//   k_redG : reduce 16 G copies, symmetrize G = G1 + G2 + G2^T (G1 mirrored)
//   k_fold : parallel fold of BN into A = a*W (bf16 hi/lo SW128) and b2
//   k_pass2: 1280 blocks (tile-halves) x 3 tiles, 256 thr, occupancy 2,
//            cp.async double-buffered, HMMA y = A@xg, affine+relu+store
// ---------------------------------------------------------------------------

#define TTOT 300
#define VV   25
#define NT   30
#define NBLK 1920
#define INV_N (1.0f / 480000.0f)

// pass1 smem layout (bytes)
#define XH1_OFF  65536   // 256 rows x 128 B
#define XL1_OFF  98304
#define ADJ1_OFF 131072  // 625 floats
#define CS2_OFF  133632  // 50 x 64 floats
#define SMEM1    146432

// skewed sX float index: c*250 + (c>>3)*2 + j   (max 16013 < 16384 floats)
#define SXI(c, j) ((c) * 250 + (((c) >> 3) << 1) + (j))

// pass2 smem layout (bytes): two 32KB half-tile buffers, then A tiles
#define P2_AH    65536
#define P2_AL    81920
#define SMEM2    98304

#define SW128(o) ((o) ^ (((o) >> 3) & 0x70))

__device__ __forceinline__ uint32_t smem_u32(const void* p) {
    uint32_t a;
    asm("{ .reg .u64 t; cvta.to.shared.u64 t, %1; cvt.u32.u64 %0, t; }" : "=r"(a) : "l"(p));
    return a;
}

#define LDSM_X4(r0, r1, r2, r3, a) \
    asm volatile("ldmatrix.sync.aligned.m8n8.x4.shared.b16 {%0,%1,%2,%3}, [%4];" \
        : "=r"(r0), "=r"(r1), "=r"(r2), "=r"(r3) : "r"(a))

#define LDSM_X4_T(r0, r1, r2, r3, a) \
    asm volatile("ldmatrix.sync.aligned.m8n8.x4.trans.shared.b16 {%0,%1,%2,%3}, [%4];" \
        : "=r"(r0), "=r"(r1), "=r"(r2), "=r"(r3) : "r"(a))

#define MMA16816(c, a0, a1, a2, a3, b0, b1) \
    asm volatile("mma.sync.aligned.m16n8k16.row.col.f32.bf16.bf16.f32 " \
        "{%0,%1,%2,%3}, {%4,%5,%6,%7}, {%8,%9}, {%0,%1,%2,%3};" \
        : "+f"((c)[0]), "+f"((c)[1]), "+f"((c)[2]), "+f"((c)[3]) \
        : "r"(a0), "r"(a1), "r"(a2), "r"(a3), "r"(b0), "r"(b1))

#define CP16(dst, src) \
    asm volatile("cp.async.cg.shared.global [%0], [%1], 16;" :: "r"(dst), "l"(src))
#define CP_COMMIT() asm volatile("cp.async.commit_group;" ::: "memory")
#define CP_WAIT(n)  asm volatile("cp.async.wait_group %0;" :: "n"(n) : "memory")

// ---- globals --------------------------------------------------------------
static __device__ float g_colsum[64];
static __device__ float g_b2[128];
static __device__ float g_G[16 * 8192];    // 16 copies x [G1 4096][G2 4096]
static __device__ float g_Gs[4096];        // symmetrized
static __device__ __align__(16) unsigned char g_AH[16384];
static __device__ __align__(16) unsigned char g_AL[16384];
static __device__ __align__(16) unsigned char g_xg[(size_t)NBLK * 65536];

__device__ __forceinline__ void split_bf16(float v, __nv_bfloat16& h, __nv_bfloat16& l) {
    h = __float2bfloat16(v);
    l = __float2bfloat16(v - __bfloat162float(h));
}

// ---------------------------------------------------------------------------
__global__ void k_z1() { if (threadIdx.x < 64) g_colsum[threadIdx.x] = 0.0f; }
__global__ void k_z2() { g_Gs[blockIdx.x * 1024 + threadIdx.x] = 0.0f; }

__global__ void k_prep() {
    int i0 = blockIdx.x * 512 + threadIdx.x;
    for (int i = i0; i < 16 * 8192; i += 16 * 512) g_G[i] = 0.0f;
}

// ---------------------------------------------------------------------------
__global__ void k_redG() {
    int idx = blockIdx.x * 1024 + threadIdx.x;   // 0..4095
    int c = idx >> 6, cp = idx & 63;
    // G1 is stored only for tile(c) <= tile(cp); mirror otherwise
    int g1idx = ((c >> 4) <= (cp >> 4)) ? idx : (cp * 64 + c);
    float s = 0.0f;
    for (int k = 0; k < 16; ++k) {
        const float* base = g_G + k * 8192;
        s += base[g1idx] + base[4096 + idx] + base[4096 + cp * 64 + c];
    }
    g_Gs[idx] = s;
}

// ---------------------------------------------------------------------------
// one block per output channel o; 64 threads (one per input channel c)
__global__ void k_fold(const float* __restrict__ W, const float* __restrict__ b,
                       const float* __restrict__ gamma, const float* __restrict__ beta) {
    __shared__ float sw[64];
    __shared__ float red_q[2], red_s[2];
    __shared__ float sa;
    const int o = blockIdx.x;
    const int c = threadIdx.x;

    sw[c] = W[o * 64 + c];
    __syncthreads();

    const float* gr = g_Gs + c * 64;
    float d = 0.0f;
#pragma unroll 8
    for (int cp = 0; cp < 64; ++cp) d = fmaf(gr[cp], sw[cp], d);

    float qv = sw[c] * d;
    float sv = sw[c] * g_colsum[c];
#pragma unroll
    for (int off = 16; off > 0; off >>= 1) {
        qv += __shfl_xor_sync(0xffffffffu, qv, off);
        sv += __shfl_xor_sync(0xffffffffu, sv, off);
    }
    if ((c & 31) == 0) { red_q[c >> 5] = qv; red_s[c >> 5] = sv; }
    __syncthreads();

    if (c == 0) {
        float q = (red_q[0] + red_q[1]) * INV_N;
        float s = (red_s[0] + red_s[1]) * INV_N;
        float var = q - s * s;
        float a = gamma[o] * rsqrtf(var + 1e-5f);
        g_b2[o] = beta[o] - a * s;
        sa = a;
    }
    __syncthreads();

    __nv_bfloat16 h, l;
    split_bf16(sa * sw[c], h, l);
    unsigned off2 = SW128((unsigned)(o * 128 + c * 2));
    *(__nv_bfloat16*)(g_AH + off2) = h;
    *(__nv_bfloat16*)(g_AL + off2) = l;
}

// ---------------------------------------------------------------------------
__global__ __launch_bounds__(512, 1) void k_pass1(const float* __restrict__ x,
                                                  const float* __restrict__ adj) {
    extern __shared__ unsigned char smem[];
    const uint32_t sb = smem_u32(smem);
    const int tid  = threadIdx.x;
    const int wid  = tid >> 5;
    const int lane = tid & 31;
    const int bx   = blockIdx.x;
    const int bb   = bx / NT;
    const int t0g  = (bx - bb * NT) * 10;

    float* sX   = (float*)smem;                 // skewed: SXI(c, j)
    float* sAdj = (float*)(smem + ADJ1_OFF);
    float* sCs2 = (float*)(smem + CS2_OFF);     // [50][64]

    // ---- x staging: float2 loads + float2 skewed stores (all 8B aligned) --
    const float* gx = x + ((size_t)bb * 64 * TTOT + t0g) * VV;
    for (int i = tid; i < 8000; i += 512) {
        int c = i / 125, j2 = (i - c * 125) * 2;
        *(float2*)(sX + SXI(c, j2)) = *(const float2*)(gx + c * (TTOT * VV) + j2);
    }
    for (int i = tid; i < 625; i += 512) sAdj[i] = adj[i];
    if (tid < 128) {  // zero pad rows 248..255 (rows 248/249 rewritten below)
        uint4 z = make_uint4(0, 0, 0, 0);
        int tile = tid >> 6, q = tid & 63;
        *(uint4*)(smem + (tile ? XL1_OFF : XH1_OFF) + 248 * 128 + q * 16) = z;
    }
    __syncthreads();

    // ---- xg = x @ adj : thread tile 8c x 5w x 1t (400 active threads) -----
    if (tid < 400) {
        const int t   = tid / 40;
        const int rem = tid - t * 40;
        const int cb  = rem / 5;
        const int wb  = rem - cb * 5;
        const int c0  = cb * 8, w0 = wb * 5;

        float accv[8][5];
#pragma unroll
        for (int cc = 0; cc < 8; ++cc)
#pragma unroll
            for (int ww = 0; ww < 5; ++ww) accv[cc][ww] = 0.0f;

        // within a thread the 8 channels share cb -> stride exactly 250
        const float* xb = sX + SXI(c0, t * 25);
#pragma unroll 5
        for (int v = 0; v < 25; ++v) {
            float xv[8];
#pragma unroll
            for (int cc = 0; cc < 8; ++cc) xv[cc] = xb[cc * 250 + v];
            float av[5];
#pragma unroll
            for (int ww = 0; ww < 5; ++ww) av[ww] = sAdj[v * 25 + w0 + ww];
#pragma unroll
            for (int cc = 0; cc < 8; ++cc)
#pragma unroll
                for (int ww = 0; ww < 5; ++ww)
                    accv[cc][ww] = fmaf(xv[cc], av[ww], accv[cc][ww]);
        }

        // packed SW128 stores: one uint4 (8 bf16) per tile per ww
#pragma unroll
        for (int ww = 0; ww < 5; ++ww) {
            int j = t * 25 + w0 + ww;
            unsigned sw = ((unsigned)(c0 * 2)) ^ (((unsigned)(j & 7)) << 4);
            uint32_t wh[4], wl[4];
#pragma unroll
            for (int k = 0; k < 4; ++k) {
                float a0 = accv[2 * k][ww], a1 = accv[2 * k + 1][ww];
                __nv_bfloat162 h2 = __floats2bfloat162_rn(a0, a1);
                float r0 = a0 - __bfloat162float(__low2bfloat16(h2));
                float r1 = a1 - __bfloat162float(__high2bfloat16(h2));
                __nv_bfloat162 l2 = __floats2bfloat162_rn(r0, r1);
                wh[k] = *(uint32_t*)&h2;
                wl[k] = *(uint32_t*)&l2;
            }
            uint4 vh = make_uint4(wh[0], wh[1], wh[2], wh[3]);
            uint4 vl = make_uint4(wl[0], wl[1], wl[2], wl[3]);
            *(uint4*)(smem + XH1_OFF + j * 128 + sw) = vh;
            *(uint4*)(smem + XL1_OFF + j * 128 + sw) = vl;
        }

        // fused colsum partials (exact fp32 xg)
        const int tile = t * 5 + wb;
#pragma unroll
        for (int cc = 0; cc < 8; ++cc) {
            float s = accv[cc][0] + accv[cc][1] + accv[cc][2] + accv[cc][3] + accv[cc][4];
            sCs2[tile * 64 + c0 + cc] = s;
        }
    }
    __syncthreads();

    // ---- colsum reduction --------------------------------------------------
    if (tid < 64) {
        float s = 0.0f;
#pragma unroll 10
        for (int k = 0; k < 50; ++k) s += sCs2[k * 64 + tid];
        atomicAdd(&g_colsum[tid], s);
    }

    // ---- spill raw split tiles to scratch ([H 32768][L 32768]) ------------
    {
        uint4* dst = (uint4*)(g_xg + (size_t)bx * 65536);
        const uint4* sH = (const uint4*)(smem + XH1_OFF);
        const uint4* sL = (const uint4*)(smem + XL1_OFF);
        for (int i = tid; i < 2048; i += 512) { dst[i] = sH[i]; dst[2048 + i] = sL[i]; }
    }

    // ---- Gram: G1 += XH.XH^T (upper tiles only, symmetric), G2 += XH.XL^T -
    {
        const int r = lane & 7, mid = lane >> 3;
        const int ti = wid & 3, tj = wid >> 2;
        const int gm0 = ti * 16;
        const int gn0 = tj * 16;
        const bool doG1 = (ti <= tj);   // skip below-diagonal G1 (mirrored in k_redG)
        float g1[2][4], g2[2][4];
#pragma unroll
        for (int i = 0; i < 2; ++i)
#pragma unroll
            for (int e = 0; e < 4; ++e) { g1[i][e] = 0.0f; g2[i][e] = 0.0f; }

#pragma unroll 4
        for (int ks = 0; ks < 16; ++ks) {
            int kb = ks * 16;
            uint32_t arow = (uint32_t)(kb + ((mid & 2) << 2) + r);
            uint32_t acol = ((uint32_t)(gm0 * 2 + ((mid & 1) << 4))) ^ (uint32_t)(r << 4);
            uint32_t brow = (uint32_t)(kb + ((mid & 1) << 3) + r);
            uint32_t bcol = ((uint32_t)(gn0 * 2 + ((mid & 2) << 3))) ^ (uint32_t)(r << 4);
            uint32_t a0, a1, a2, a3, bl0, bl1, bl2, bl3;
            LDSM_X4_T(a0, a1, a2, a3, sb + XH1_OFF + arow * 128 + acol);
            LDSM_X4_T(bl0, bl1, bl2, bl3, sb + XL1_OFF + brow * 128 + bcol);
            if (doG1) {
                uint32_t bh0, bh1, bh2, bh3;
                LDSM_X4_T(bh0, bh1, bh2, bh3, sb + XH1_OFF + brow * 128 + bcol);
                MMA16816(g1[0], a0, a1, a2, a3, bh0, bh1);
                MMA16816(g1[1], a0, a1, a2, a3, bh2, bh3);
            }
            MMA16816(g2[0], a0, a1, a2, a3, bl0, bl1);
            MMA16816(g2[1], a0, a1, a2, a3, bl2, bl3);
        }

        float* Gc  = g_G + (size_t)((bx & 15) * 8192);
        float* G2c = Gc + 4096;
        int rr = gm0 + (lane >> 2);
        int cc = gn0 + (lane & 3) * 2;
#pragma unroll
        for (int nf = 0; nf < 2; ++nf) {
            int cb2 = cc + nf * 8;
            if (doG1) {
                atomicAdd(Gc + rr * 64 + cb2,           g1[nf][0]);
                atomicAdd(Gc + rr * 64 + cb2 + 1,       g1[nf][1]);
                atomicAdd(Gc + (rr + 8) * 64 + cb2,     g1[nf][2]);
                atomicAdd(Gc + (rr + 8) * 64 + cb2 + 1, g1[nf][3]);
            }
            atomicAdd(G2c + rr * 64 + cb2,           g2[nf][0]);
            atomicAdd(G2c + rr * 64 + cb2 + 1,       g2[nf][1]);
            atomicAdd(G2c + (rr + 8) * 64 + cb2,     g2[nf][2]);
            atomicAdd(G2c + (rr + 8) * 64 + cb2 + 1, g2[nf][3]);
        }
    }
}

// ---------------------------------------------------------------------------
__global__ __launch_bounds__(256, 2) void k_pass2(float* __restrict__ out) {
    extern __shared__ unsigned char smem[];
    const uint32_t sb = smem_u32(smem);
    const int tid  = threadIdx.x;
    const int wid  = tid >> 5;     // 0..7
    const int lane = tid & 31;
    const int p    = blockIdx.x >> 1;
    const int hb   = blockIdx.x & 1;    // which 128-col half of the tile

    // group 0: A tiles + half-tile 0
    for (int i = tid; i < 1024; i += 256) {
        CP16(sb + P2_AH + i * 16, g_AH + i * 16);
        CP16(sb + P2_AL + i * 16, g_AL + i * 16);
    }
    {
        const unsigned char* base = g_xg + (size_t)(p * 3) * 65536 + hb * 16384;
        for (int i = tid; i < 1024; i += 256) {
            CP16(sb + i * 16,         base + i * 16);           // XH half
            CP16(sb + 16384 + i * 16, base + 32768 + i * 16);   // XL half
        }
        CP_COMMIT();
    }

    const int r   = lane & 7;
    const int mid = lane >> 3;
    const int m0  = (wid & 3) * 32;
    const int nl0 = (wid >> 2) * 64;    // local col group (0 or 64)
    const int swx = r << 4;

    uint32_t a_rowoff[2], b_rowoff[4];
#pragma unroll
    for (int mt = 0; mt < 2; ++mt)
        a_rowoff[mt] = (uint32_t)(m0 + mt * 16 + ((mid & 1) << 3) + r) * 128u;
#pragma unroll
    for (int np = 0; np < 4; ++np)
        b_rowoff[np] = (uint32_t)(nl0 + np * 16 + ((mid & 2) << 2) + r) * 128u;

    float bz[2][2];
#pragma unroll
    for (int mt = 0; mt < 2; ++mt) {
        int row0 = m0 + mt * 16 + (lane >> 2);
        bz[mt][0] = g_b2[row0];
        bz[mt][1] = g_b2[row0 + 8];
    }

    for (int it = 0; it < 3; ++it) {
        if (it < 2) {
            const unsigned char* base = g_xg + (size_t)(p * 3 + it + 1) * 65536 + hb * 16384;
            uint32_t db = sb + (uint32_t)(((it + 1) & 1) * 32768);
            for (int i = tid; i < 1024; i += 256) {
                CP16(db + i * 16,         base + i * 16);
                CP16(db + 16384 + i * 16, base + 32768 + i * 16);
            }
            CP_COMMIT();
            CP_WAIT(1);
        } else {
            CP_WAIT(0);
        }
        __syncthreads();

        const uint32_t xh = sb + (uint32_t)((it & 1) * 32768);
        const uint32_t xl = xh + 16384u;
        const uint32_t Ab[3] = {sb + P2_AH, sb + P2_AH, sb + P2_AL};
        const uint32_t Bb[3] = {xh, xl, xh};

        float acc[2][8][4];
#pragma unroll
        for (int mt = 0; mt < 2; ++mt)
#pragma unroll
            for (int nt = 0; nt < 8; ++nt)
#pragma unroll
                for (int e = 0; e < 4; ++e) acc[mt][nt][e] = 0.0f;

#pragma unroll
        for (int pr = 0; pr < 3; ++pr) {
            const uint32_t Abase = Ab[pr];
            const uint32_t Bbase = Bb[pr];
#pragma unroll
            for (int ks = 0; ks < 4; ++ks) {
                const uint32_t ca = (uint32_t)(ks * 32 + ((mid & 2) << 3)) ^ swx;
                const uint32_t cb = (uint32_t)(ks * 32 + ((mid & 1) << 4)) ^ swx;
                uint32_t a[2][4];
#pragma unroll
                for (int mt = 0; mt < 2; ++mt)
                    LDSM_X4(a[mt][0], a[mt][1], a[mt][2], a[mt][3],
                            Abase + a_rowoff[mt] + ca);
#pragma unroll
                for (int np = 0; np < 4; ++np) {
                    uint32_t b0, b1, b2, b3;
                    LDSM_X4(b0, b1, b2, b3, Bbase + b_rowoff[np] + cb);
                    MMA16816(acc[0][2 * np],     a[0][0], a[0][1], a[0][2], a[0][3], b0, b1);
                    MMA16816(acc[0][2 * np + 1], a[0][0], a[0][1], a[0][2], a[0][3], b2, b3);
                    MMA16816(acc[1][2 * np],     a[1][0], a[1][1], a[1][2], a[1][3], b0, b1);
                    MMA16816(acc[1][2 * np + 1], a[1][0], a[1][1], a[1][2], a[1][3], b2, b3);
                }
            }
        }

        const int tt = p * 3 + it;
        const int bb = tt / NT;
        const int t0 = (tt - bb * NT) * 10;
#pragma unroll
        for (int mt = 0; mt < 2; ++mt) {
            int row0 = m0 + mt * 16 + (lane >> 2);
            float* base0 = out + ((size_t)(bb * 128 + row0)) * (TTOT * VV) + t0 * VV;
            float* base1 = base0 + 8 * (TTOT * VV);
#pragma unroll
            for (int nt = 0; nt < 8; ++nt) {
                int j = hb * 128 + nl0 + nt * 8 + (lane & 3) * 2;
                if (j < 250) {
                    float2 v0, v1;
                    v0.x = fmaxf(acc[mt][nt][0] + bz[mt][0], 0.0f);
                    v0.y = fmaxf(acc[mt][nt][1] + bz[mt][0], 0.0f);
                    v1.x = fmaxf(acc[mt][nt][2] + bz[mt][1], 0.0f);
                    v1.y = fmaxf(acc[mt][nt][3] + bz[mt][1], 0.0f);
                    *(float2*)(base0 + j) = v0;
                    *(float2*)(base1 + j) = v1;
                }
            }
        }
        __syncthreads();
    }
}

// ---------------------------------------------------------------------------
extern "C" void kernel_launch(void* const* d_in, const int* in_sizes, int n_in,
                              void* d_out, int out_size) {
    const float* x     = (const float*)d_in[0];
    const float* adj   = (const float*)d_in[1];
    const float* W     = (const float*)d_in[2];
    const float* b     = (const float*)d_in[3];
    const float* gamma = (const float*)d_in[4];
    const float* beta  = (const float*)d_in[5];
    float* out = (float*)d_out;

    cudaFuncSetAttribute(k_pass1, cudaFuncAttributeMaxDynamicSharedMemorySize, SMEM1);
    cudaFuncSetAttribute(k_pass2, cudaFuncAttributeMaxDynamicSharedMemorySize, SMEM2);

    k_z1<<<1, 64>>>();
    k_z2<<<4, 1024>>>();
    k_prep<<<16, 512>>>();
    k_pass1<<<NBLK, 512, SMEM1>>>(x, adj);
    k_redG<<<4, 1024>>>();
    k_fold<<<128, 64>>>(W, b, gamma, beta);
    k_pass2<<<1280, 256, SMEM2>>>(out);
}

// round 14
// speedup vs baseline: 1.1035x; 1.1035x over previous
#include <cuda_runtime.h>
#include <cuda_bf16.h>
#include <cstdint>

// ---------------------------------------------------------------------------
// SpatialGraphConv (R10 structure + fused direct spill):
//   k_z1/k_z2: zero colsum / Gs (keeps ncu capture slot on k_pass1)
//   k_prep : zero G copies
//   k_pass1: x tile -> xg = x@adj (8c x 5w reg tiles) -> split bf16 ->
//            packed uint4 SW128 stores to smem AND directly to scratch
//            (no separate spill phase); fused exact colsum; Gram via HMMA
//            (below-diagonal G1 skipped, mirrored in k_redG)
//   k_redG : reduce 16 G copies, symmetrize G = G1 + G2 + G2^T (G1 mirrored)
//   k_fold : parallel fold of BN into A = a*W (bf16 hi/lo SW128) and b2
//   k_pass2: 1280 blocks (tile-halves) x 3 tiles, 256 thr, occupancy 2,
//            cp.async double-buffered, HMMA y = A@xg, affine+relu+store
// ---------------------------------------------------------------------------

#define TTOT 300
#define VV   25
#define NT   30
#define NBLK 1920
#define INV_N (1.0f / 480000.0f)

// pass1 smem layout (bytes)
#define XH1_OFF  65536   // 256 rows x 128 B
#define XL1_OFF  98304
#define ADJ1_OFF 131072  // 625 floats
#define CS2_OFF  133632  // 50 x 64 floats
#define SMEM1    146432
#define XPITCH   251     // sX row pitch in floats

// pass2 smem layout (bytes): two 32KB half-tile buffers, then A tiles
#define P2_AH    65536
#define P2_AL    81920
#define SMEM2    98304

#define SW128(o) ((o) ^ (((o) >> 3) & 0x70))

__device__ __forceinline__ uint32_t smem_u32(const void* p) {
    uint32_t a;
    asm("{ .reg .u64 t; cvta.to.shared.u64 t, %1; cvt.u32.u64 %0, t; }" : "=r"(a) : "l"(p));
    return a;
}

#define LDSM_X4(r0, r1, r2, r3, a) \
    asm volatile("ldmatrix.sync.aligned.m8n8.x4.shared.b16 {%0,%1,%2,%3}, [%4];" \
        : "=r"(r0), "=r"(r1), "=r"(r2), "=r"(r3) : "r"(a))

#define LDSM_X4_T(r0, r1, r2, r3, a) \
    asm volatile("ldmatrix.sync.aligned.m8n8.x4.trans.shared.b16 {%0,%1,%2,%3}, [%4];" \
        : "=r"(r0), "=r"(r1), "=r"(r2), "=r"(r3) : "r"(a))

#define MMA16816(c, a0, a1, a2, a3, b0, b1) \
    asm volatile("mma.sync.aligned.m16n8k16.row.col.f32.bf16.bf16.f32 " \
        "{%0,%1,%2,%3}, {%4,%5,%6,%7}, {%8,%9}, {%0,%1,%2,%3};" \
        : "+f"((c)[0]), "+f"((c)[1]), "+f"((c)[2]), "+f"((c)[3]) \
        : "r"(a0), "r"(a1), "r"(a2), "r"(a3), "r"(b0), "r"(b1))

#define CP16(dst, src) \
    asm volatile("cp.async.cg.shared.global [%0], [%1], 16;" :: "r"(dst), "l"(src))
#define CP_COMMIT() asm volatile("cp.async.commit_group;" ::: "memory")
#define CP_WAIT(n)  asm volatile("cp.async.wait_group %0;" :: "n"(n) : "memory")

// ---- globals --------------------------------------------------------------
static __device__ float g_colsum[64];
static __device__ float g_b2[128];
static __device__ float g_G[16 * 8192];    // 16 copies x [G1 4096][G2 4096]
static __device__ float g_Gs[4096];        // symmetrized
static __device__ __align__(16) unsigned char g_AH[16384];
static __device__ __align__(16) unsigned char g_AL[16384];
static __device__ __align__(16) unsigned char g_xg[(size_t)NBLK * 65536];

__device__ __forceinline__ void split_bf16(float v, __nv_bfloat16& h, __nv_bfloat16& l) {
    h = __float2bfloat16(v);
    l = __float2bfloat16(v - __bfloat162float(h));
}

// ---------------------------------------------------------------------------
__global__ void k_z1() { if (threadIdx.x < 64) g_colsum[threadIdx.x] = 0.0f; }
__global__ void k_z2() { g_Gs[blockIdx.x * 1024 + threadIdx.x] = 0.0f; }

__global__ void k_prep() {
    int i0 = blockIdx.x * 512 + threadIdx.x;
    for (int i = i0; i < 16 * 8192; i += 16 * 512) g_G[i] = 0.0f;
}

// ---------------------------------------------------------------------------
__global__ void k_redG() {
    int idx = blockIdx.x * 1024 + threadIdx.x;   // 0..4095
    int c = idx >> 6, cp = idx & 63;
    // G1 is stored only for tile(c) <= tile(cp); mirror otherwise
    int g1idx = ((c >> 4) <= (cp >> 4)) ? idx : (cp * 64 + c);
    float s = 0.0f;
    for (int k = 0; k < 16; ++k) {
        const float* base = g_G + k * 8192;
        s += base[g1idx] + base[4096 + idx] + base[4096 + cp * 64 + c];
    }
    g_Gs[idx] = s;
}

// ---------------------------------------------------------------------------
// one block per output channel o; 64 threads (one per input channel c)
__global__ void k_fold(const float* __restrict__ W, const float* __restrict__ b,
                       const float* __restrict__ gamma, const float* __restrict__ beta) {
    __shared__ float sw[64];
    __shared__ float red_q[2], red_s[2];
    __shared__ float sa;
    const int o = blockIdx.x;
    const int c = threadIdx.x;

    sw[c] = W[o * 64 + c];
    __syncthreads();

    const float* gr = g_Gs + c * 64;
    float d = 0.0f;
#pragma unroll 8
    for (int cp = 0; cp < 64; ++cp) d = fmaf(gr[cp], sw[cp], d);

    float qv = sw[c] * d;
    float sv = sw[c] * g_colsum[c];
#pragma unroll
    for (int off = 16; off > 0; off >>= 1) {
        qv += __shfl_xor_sync(0xffffffffu, qv, off);
        sv += __shfl_xor_sync(0xffffffffu, sv, off);
    }
    if ((c & 31) == 0) { red_q[c >> 5] = qv; red_s[c >> 5] = sv; }
    __syncthreads();

    if (c == 0) {
        float q = (red_q[0] + red_q[1]) * INV_N;
        float s = (red_s[0] + red_s[1]) * INV_N;
        float var = q - s * s;
        float a = gamma[o] * rsqrtf(var + 1e-5f);
        g_b2[o] = beta[o] - a * s;
        sa = a;
    }
    __syncthreads();

    __nv_bfloat16 h, l;
    split_bf16(sa * sw[c], h, l);
    unsigned off2 = SW128((unsigned)(o * 128 + c * 2));
    *(__nv_bfloat16*)(g_AH + off2) = h;
    *(__nv_bfloat16*)(g_AL + off2) = l;
}

// ---------------------------------------------------------------------------
__global__ __launch_bounds__(512, 1) void k_pass1(const float* __restrict__ x,
                                                  const float* __restrict__ adj) {
    extern __shared__ unsigned char smem[];
    const uint32_t sb = smem_u32(smem);
    const int tid  = threadIdx.x;
    const int wid  = tid >> 5;
    const int lane = tid & 31;
    const int bx   = blockIdx.x;
    const int bb   = bx / NT;
    const int t0g  = (bx - bb * NT) * 10;

    float* sX   = (float*)smem;                 // [c][XPITCH]
    float* sAdj = (float*)(smem + ADJ1_OFF);
    float* sCs2 = (float*)(smem + CS2_OFF);     // [50][64]

    unsigned char* scratch = g_xg + (size_t)bx * 65536;   // [H 32768][L 32768]

    const float* gx = x + ((size_t)bb * 64 * TTOT + t0g) * VV;
    for (int i = tid; i < 16000; i += 512) {
        int c = i / 250, j = i - c * 250;
        sX[c * XPITCH + j] = gx[c * (TTOT * VV) + j];
    }
    for (int i = tid; i < 625; i += 512) sAdj[i] = adj[i];
    if (tid < 128) {  // zero smem pad rows 248..255 (248/249 rewritten below)
        uint4 z = make_uint4(0, 0, 0, 0);
        int tile = tid >> 6, q = tid & 63;
        *(uint4*)(smem + (tile ? XL1_OFF : XH1_OFF) + 248 * 128 + q * 16) = z;
    } else if (tid < 224) {  // zero scratch pad rows 250..255 (H and L)
        uint4 z = make_uint4(0, 0, 0, 0);
        int k = tid - 128;          // 0..95
        int tile = k / 48, rr = k - tile * 48;
        int row = 250 + (rr >> 3), q = rr & 7;
        *(uint4*)(scratch + tile * 32768 + row * 128 + q * 16) = z;
    }
    __syncthreads();

    // ---- xg = x @ adj : thread tile 8c x 5w x 1t (400 active threads) -----
    // split stores go to smem (for Gram) AND directly to scratch (for pass2)
    if (tid < 400) {
        const int t   = tid / 40;
        const int rem = tid - t * 40;
        const int cb  = rem / 5;
        const int wb  = rem - cb * 5;
        const int c0  = cb * 8, w0 = wb * 5;

        float accv[8][5];
#pragma unroll
        for (int cc = 0; cc < 8; ++cc)
#pragma unroll
            for (int ww = 0; ww < 5; ++ww) accv[cc][ww] = 0.0f;

        const float* xb = sX + c0 * XPITCH + t * 25;
#pragma unroll 5
        for (int v = 0; v < 25; ++v) {
            float xv[8];
#pragma unroll
            for (int cc = 0; cc < 8; ++cc) xv[cc] = xb[cc * XPITCH + v];
            float av[5];
#pragma unroll
            for (int ww = 0; ww < 5; ++ww) av[ww] = sAdj[v * 25 + w0 + ww];
#pragma unroll
            for (int cc = 0; cc < 8; ++cc)
#pragma unroll
                for (int ww = 0; ww < 5; ++ww)
                    accv[cc][ww] = fmaf(xv[cc], av[ww], accv[cc][ww]);
        }

        // packed SW128 stores: one uint4 (8 bf16) per tile per ww
#pragma unroll
        for (int ww = 0; ww < 5; ++ww) {
            int j = t * 25 + w0 + ww;
            unsigned sw = ((unsigned)(c0 * 2)) ^ (((unsigned)(j & 7)) << 4);
            unsigned off = (unsigned)(j * 128) + sw;
            uint32_t wh[4], wl[4];
#pragma unroll
            for (int k = 0; k < 4; ++k) {
                float a0 = accv[2 * k][ww], a1 = accv[2 * k + 1][ww];
                __nv_bfloat162 h2 = __floats2bfloat162_rn(a0, a1);
                float r0 = a0 - __bfloat162float(__low2bfloat16(h2));
                float r1 = a1 - __bfloat162float(__high2bfloat16(h2));
                __nv_bfloat162 l2 = __floats2bfloat162_rn(r0, r1);
                wh[k] = *(uint32_t*)&h2;
                wl[k] = *(uint32_t*)&l2;
            }
            uint4 vh = make_uint4(wh[0], wh[1], wh[2], wh[3]);
            uint4 vl = make_uint4(wl[0], wl[1], wl[2], wl[3]);
            *(uint4*)(smem + XH1_OFF + off) = vh;
            *(uint4*)(smem + XL1_OFF + off) = vl;
            *(uint4*)(scratch + off)         = vh;   // fused direct spill
            *(uint4*)(scratch + 32768 + off) = vl;
        }

        // fused colsum partials (exact fp32 xg)
        const int tile = t * 5 + wb;
#pragma unroll
        for (int cc = 0; cc < 8; ++cc) {
            float s = accv[cc][0] + accv[cc][1] + accv[cc][2] + accv[cc][3] + accv[cc][4];
            sCs2[tile * 64 + c0 + cc] = s;
        }
    }
    __syncthreads();

    // ---- colsum reduction --------------------------------------------------
    if (tid < 64) {
        float s = 0.0f;
#pragma unroll 10
        for (int k = 0; k < 50; ++k) s += sCs2[k * 64 + tid];
        atomicAdd(&g_colsum[tid], s);
    }

    // ---- Gram: G1 += XH.XH^T (upper tiles only, symmetric), G2 += XH.XL^T -
    {
        const int r = lane & 7, mid = lane >> 3;
        const int ti = wid & 3, tj = wid >> 2;
        const int gm0 = ti * 16;
        const int gn0 = tj * 16;
        const bool doG1 = (ti <= tj);   // skip below-diagonal G1 (mirrored in k_redG)
        float g1[2][4], g2[2][4];
#pragma unroll
        for (int i = 0; i < 2; ++i)
#pragma unroll
            for (int e = 0; e < 4; ++e) { g1[i][e] = 0.0f; g2[i][e] = 0.0f; }

#pragma unroll 4
        for (int ks = 0; ks < 16; ++ks) {
            int kb = ks * 16;
            uint32_t arow = (uint32_t)(kb + ((mid & 2) << 2) + r);
            uint32_t acol = ((uint32_t)(gm0 * 2 + ((mid & 1) << 4))) ^ (uint32_t)(r << 4);
            uint32_t brow = (uint32_t)(kb + ((mid & 1) << 3) + r);
            uint32_t bcol = ((uint32_t)(gn0 * 2 + ((mid & 2) << 3))) ^ (uint32_t)(r << 4);
            uint32_t a0, a1, a2, a3, bl0, bl1, bl2, bl3;
            LDSM_X4_T(a0, a1, a2, a3, sb + XH1_OFF + arow * 128 + acol);
            LDSM_X4_T(bl0, bl1, bl2, bl3, sb + XL1_OFF + brow * 128 + bcol);
            if (doG1) {
                uint32_t bh0, bh1, bh2, bh3;
                LDSM_X4_T(bh0, bh1, bh2, bh3, sb + XH1_OFF + brow * 128 + bcol);
                MMA16816(g1[0], a0, a1, a2, a3, bh0, bh1);
                MMA16816(g1[1], a0, a1, a2, a3, bh2, bh3);
            }
            MMA16816(g2[0], a0, a1, a2, a3, bl0, bl1);
            MMA16816(g2[1], a0, a1, a2, a3, bl2, bl3);
        }

        float* Gc  = g_G + (size_t)((bx & 15) * 8192);
        float* G2c = Gc + 4096;
        int rr = gm0 + (lane >> 2);
        int cc = gn0 + (lane & 3) * 2;
#pragma unroll
        for (int nf = 0; nf < 2; ++nf) {
            int cb2 = cc + nf * 8;
            if (doG1) {
                atomicAdd(Gc + rr * 64 + cb2,           g1[nf][0]);
                atomicAdd(Gc + rr * 64 + cb2 + 1,       g1[nf][1]);
                atomicAdd(Gc + (rr + 8) * 64 + cb2,     g1[nf][2]);
                atomicAdd(Gc + (rr + 8) * 64 + cb2 + 1, g1[nf][3]);
            }
            atomicAdd(G2c + rr * 64 + cb2,           g2[nf][0]);
            atomicAdd(G2c + rr * 64 + cb2 + 1,       g2[nf][1]);
            atomicAdd(G2c + (rr + 8) * 64 + cb2,     g2[nf][2]);
            atomicAdd(G2c + (rr + 8) * 64 + cb2 + 1, g2[nf][3]);
        }
    }
}

// ---------------------------------------------------------------------------
__global__ __launch_bounds__(256, 2) void k_pass2(float* __restrict__ out) {
    extern __shared__ unsigned char smem[];
    const uint32_t sb = smem_u32(smem);
    const int tid  = threadIdx.x;
    const int wid  = tid >> 5;     // 0..7
    const int lane = tid & 31;
    const int p    = blockIdx.x >> 1;
    const int hb   = blockIdx.x & 1;    // which 128-col half of the tile

    // group 0: A tiles + half-tile 0
    for (int i = tid; i < 1024; i += 256) {
        CP16(sb + P2_AH + i * 16, g_AH + i * 16);
        CP16(sb + P2_AL + i * 16, g_AL + i * 16);
    }
    {
        const unsigned char* base = g_xg + (size_t)(p * 3) * 65536 + hb * 16384;
        for (int i = tid; i < 1024; i += 256) {
            CP16(sb + i * 16,         base + i * 16);           // XH half
            CP16(sb + 16384 + i * 16, base + 32768 + i * 16);   // XL half
        }
        CP_COMMIT();
    }

    const int r   = lane & 7;
    const int mid = lane >> 3;
    const int m0  = (wid & 3) * 32;
    const int nl0 = (wid >> 2) * 64;    // local col group (0 or 64)
    const int swx = r << 4;

    uint32_t a_rowoff[2], b_rowoff[4];
#pragma unroll
    for (int mt = 0; mt < 2; ++mt)
        a_rowoff[mt] = (uint32_t)(m0 + mt * 16 + ((mid & 1) << 3) + r) * 128u;
#pragma unroll
    for (int np = 0; np < 4; ++np)
        b_rowoff[np] = (uint32_t)(nl0 + np * 16 + ((mid & 2) << 2) + r) * 128u;

    float bz[2][2];
#pragma unroll
    for (int mt = 0; mt < 2; ++mt) {
        int row0 = m0 + mt * 16 + (lane >> 2);
        bz[mt][0] = g_b2[row0];
        bz[mt][1] = g_b2[row0 + 8];
    }

    for (int it = 0; it < 3; ++it) {
        if (it < 2) {
            const unsigned char* base = g_xg + (size_t)(p * 3 + it + 1) * 65536 + hb * 16384;
            uint32_t db = sb + (uint32_t)(((it + 1) & 1) * 32768);
            for (int i = tid; i < 1024; i += 256) {
                CP16(db + i * 16,         base + i * 16);
                CP16(db + 16384 + i * 16, base + 32768 + i * 16);
            }
            CP_COMMIT();
            CP_WAIT(1);
        } else {
            CP_WAIT(0);
        }
        __syncthreads();

        const uint32_t xh = sb + (uint32_t)((it & 1) * 32768);
        const uint32_t xl = xh + 16384u;
        const uint32_t Ab[3] = {sb + P2_AH, sb + P2_AH, sb + P2_AL};
        const uint32_t Bb[3] = {xh, xl, xh};

        float acc[2][8][4];
#pragma unroll
        for (int mt = 0; mt < 2; ++mt)
#pragma unroll
            for (int nt = 0; nt < 8; ++nt)
#pragma unroll
                for (int e = 0; e < 4; ++e) acc[mt][nt][e] = 0.0f;

#pragma unroll
        for (int pr = 0; pr < 3; ++pr) {
            const uint32_t Abase = Ab[pr];
            const uint32_t Bbase = Bb[pr];
#pragma unroll
            for (int ks = 0; ks < 4; ++ks) {
                const uint32_t ca = (uint32_t)(ks * 32 + ((mid & 2) << 3)) ^ swx;
                const uint32_t cb = (uint32_t)(ks * 32 + ((mid & 1) << 4)) ^ swx;
                uint32_t a[2][4];
#pragma unroll
                for (int mt = 0; mt < 2; ++mt)
                    LDSM_X4(a[mt][0], a[mt][1], a[mt][2], a[mt][3],
                            Abase + a_rowoff[mt] + ca);
#pragma unroll
                for (int np = 0; np < 4; ++np) {
                    uint32_t b0, b1, b2, b3;
                    LDSM_X4(b0, b1, b2, b3, Bbase + b_rowoff[np] + cb);
                    MMA16816(acc[0][2 * np],     a[0][0], a[0][1], a[0][2], a[0][3], b0, b1);
                    MMA16816(acc[0][2 * np + 1], a[0][0], a[0][1], a[0][2], a[0][3], b2, b3);
                    MMA16816(acc[1][2 * np],     a[1][0], a[1][1], a[1][2], a[1][3], b0, b1);
                    MMA16816(acc[1][2 * np + 1], a[1][0], a[1][1], a[1][2], a[1][3], b2, b3);
                }
            }
        }

        const int tt = p * 3 + it;
        const int bb = tt / NT;
        const int t0 = (tt - bb * NT) * 10;
#pragma unroll
        for (int mt = 0; mt < 2; ++mt) {
            int row0 = m0 + mt * 16 + (lane >> 2);
            float* base0 = out + ((size_t)(bb * 128 + row0)) * (TTOT * VV) + t0 * VV;
            float* base1 = base0 + 8 * (TTOT * VV);
#pragma unroll
            for (int nt = 0; nt < 8; ++nt) {
                int j = hb * 128 + nl0 + nt * 8 + (lane & 3) * 2;
                if (j < 250) {
                    float2 v0, v1;
                    v0.x = fmaxf(acc[mt][nt][0] + bz[mt][0], 0.0f);
                    v0.y = fmaxf(acc[mt][nt][1] + bz[mt][0], 0.0f);
                    v1.x = fmaxf(acc[mt][nt][2] + bz[mt][1], 0.0f);
                    v1.y = fmaxf(acc[mt][nt][3] + bz[mt][1], 0.0f);
                    *(float2*)(base0 + j) = v0;
                    *(float2*)(base1 + j) = v1;
                }
            }
        }
        __syncthreads();
    }
}

// ---------------------------------------------------------------------------
extern "C" void kernel_launch(void* const* d_in, const int* in_sizes, int n_in,
                              void* d_out, int out_size) {
    const float* x     = (const float*)d_in[0];
    const float* adj   = (const float*)d_in[1];
    const float* W     = (const float*)d_in[2];
    const float* b     = (const float*)d_in[3];
    const float* gamma = (const float*)d_in[4];
    const float* beta  = (const float*)d_in[5];
    float* out = (float*)d_out;

    cudaFuncSetAttribute(k_pass1, cudaFuncAttributeMaxDynamicSharedMemorySize, SMEM1);
    cudaFuncSetAttribute(k_pass2, cudaFuncAttributeMaxDynamicSharedMemorySize, SMEM2);

    k_z1<<<1, 64>>>();
    k_z2<<<4, 1024>>>();
    k_prep<<<16, 512>>>();
    k_pass1<<<NBLK, 512, SMEM1>>>(x, adj);
    k_redG<<<4, 1024>>>();
    k_fold<<<128, 64>>>(W, b, gamma, beta);
    k_pass2<<<1280, 256, SMEM2>>>(out);
}